// round 10
// baseline (speedup 1.0000x reference)
#include <cuda_runtime.h>
#include <math.h>

// Petrosian fractal features, 5 scales, T=4096, 57 windows/row.
// cp.async double-buffered smem pipeline: each CTA streams 8 consecutive rows
// (16KB each), one full row + next always in flight (L1-bypassed cp.async.cg).
// Compute: thread t owns elems [16t,16t+16) + 2-elem halo, all read from smem
// with a +16B/128B padded layout (conflict-free LDS.128). Segment sums (128
// elems = 8 threads) via one __reduce_add_sync; warp 0 scans 32 segments in
// registers and emits all 57 windows:
//   zc([128a,128b)) = S[b] - S[a] - (s[128b-2]+s[128b-1])

#define T_LEN   4096
#define N_WIN   57
#define RPC     8            // rows per CTA
#define THREADS 256
#define FULL    0xffffffffu
#define ROW_PADDED 4608      // 4096 words + 4 pad words per 32

__device__ __forceinline__ unsigned smem_u32(const void* p) {
    return (unsigned)__cvta_generic_to_shared(p);
}
template<int N>
__device__ __forceinline__ void cp_wait_group() {
    asm volatile("cp.async.wait_group %0;\n" :: "n"(N) : "memory");
}
__device__ __forceinline__ void cp16(unsigned daddr, const void* src) {
    asm volatile("cp.async.cg.shared.global [%0], [%1], 16;\n"
                 :: "r"(daddr), "l"(src) : "memory");
}
__device__ __forceinline__ void cp_commit() {
    asm volatile("cp.async.commit_group;\n" ::: "memory");
}

__global__ __launch_bounds__(THREADS)
void petrosian_kernel(const float* __restrict__ x, float* __restrict__ out) {
    __shared__ __align__(16) float buf[2][ROW_PADDED];
    __shared__ int segsum[32];
    __shared__ int bcs[33];

    const int tid  = threadIdx.x;
    const int lane = tid & 31;
    const int wid  = tid >> 5;
    const float* grow = x + (size_t)blockIdx.x * RPC * T_LEN;

    auto issue = [&](int r, int st) {
        unsigned sb = smem_u32(&buf[st][0]);
        const float* g = grow + r * T_LEN;
        #pragma unroll
        for (int i = 0; i < 4; i++) {
            int chunk = i * 256 + tid;            // 16B-chunk index (coalesced)
            int w  = 4 * chunk;                   // word index in row
            int pw = w + ((w >> 5) << 2);         // padded word index
            cp16(sb + pw * 4, g + w);
        }
        cp_commit();
    };

    issue(0, 0);
    issue(1, 1);

    #pragma unroll
    for (int r = 0; r < RPC; r++) {
        if (r < RPC - 1) cp_wait_group<1>(); else cp_wait_group<0>();
        __syncthreads();                          // row r resident; prev tail done

        // ---- compute row r from stage r&1 ----
        const float* b = buf[r & 1];
        const int base = tid * 16;
        float v[18];
        #pragma unroll
        for (int i = 0; i < 4; i++) {
            int w = base + 4 * i;
            int pw = w + ((w >> 5) << 2);
            float4 t4 = *(const float4*)(b + pw);
            v[4*i] = t4.x; v[4*i+1] = t4.y; v[4*i+2] = t4.z; v[4*i+3] = t4.w;
        }
        if (tid < THREADS - 1) {
            int w = base + 16;
            int pw = w + ((w >> 5) << 2);
            float2 h = *(const float2*)(b + pw);
            v[16] = h.x; v[17] = h.y;
        } else { v[16] = 0.0f; v[17] = 0.0f; }

        int cnt = 0, s14 = 0, s15 = 0;
        float dp = v[1] - v[0];
        #pragma unroll
        for (int i = 0; i < 16; i++) {
            float dn = v[i + 2] - v[i + 1];
            int s = (dp * dn < 0.0f) ? 1 : 0;
            if (i >= 14 && tid == THREADS - 1) s = 0;   // j = 4094,4095 invalid
            cnt += s;
            if (i == 14) s14 = s;
            if (i == 15) s15 = s;
            dp = dn;
        }

        unsigned gmask = 0xFFu << (lane & 24);
        int ssum = __reduce_add_sync(gmask, cnt);
        if ((tid & 7) == 7) {
            segsum[tid >> 3] = ssum;
            bcs[(tid >> 3) + 1] = s14 + s15;      // bcs[32] = 0 via forced s
        }
        __syncthreads();                          // segsum/bcs visible; reads done

        // ---- refill freed stage with row r+2 ----
        if (r + 2 < RPC) issue(r + 2, r & 1);

        // ---- warp 0: scan + emit 57 outputs for row r ----
        if (wid == 0) {
            int sc = segsum[lane];
            #pragma unroll
            for (int off = 1; off < 32; off <<= 1) {
                int n = __shfl_up_sync(FULL, sc, off);
                if (lane >= off) sc += n;         // sc = S[lane+1]
            }
            const size_t obase = ((size_t)blockIdx.x * RPC + r) * N_WIN;
            #pragma unroll
            for (int half = 0; half < 2; half++) {
                int k  = lane + half * 32;
                int kk = (k < N_WIN) ? k : 0;
                int w, a; float L;
                if      (kk < 1)  { w = 4096; a = 0;             L = 3.612359948f; }
                else if (kk < 4)  { w = 2048; a = (kk - 1) * 8;  L = 3.311329954f; }
                else if (kk < 11) { w = 1024; a = (kk - 4) * 4;  L = 3.010299957f; }
                else if (kk < 26) { w = 512;  a = (kk - 11) * 2; L = 2.709269961f; }
                else              { w = 256;  a = kk - 26;       L = 2.408239965f; }
                int bwin = a + (w >> 7);

                int Sb = __shfl_sync(FULL, sc, bwin - 1);
                int Sa = __shfl_sync(FULL, sc, (a > 0) ? (a - 1) : 0);
                if (a == 0) Sa = 0;

                if (k < N_WIN) {
                    float zc = (float)(Sb - Sa - bcs[bwin]);
                    float wf = (float)w;
                    float denom = L + log10f(wf / (wf + 0.4f * zc));
                    out[obase + k] = L / denom;
                }
            }
        }
    }
}

extern "C" void kernel_launch(void* const* d_in, const int* in_sizes, int n_in,
                              void* d_out, int out_size) {
    const float* x = (const float*)d_in[0];
    float* out = (float*)d_out;
    int n_rows = in_sizes[0] / T_LEN;     // 4096
    int n_blocks = n_rows / RPC;          // 512
    petrosian_kernel<<<n_blocks, THREADS>>>(x, out);
}

// round 11
// speedup vs baseline: 1.5013x; 1.5013x over previous
#include <cuda_runtime.h>
#include <math.h>

// Petrosian fractal features, 5 scales, T=4096, 57 windows/row.
// One WARP per row, 8 rows/CTA, no smem, no __syncthreads.
// Row = 16 chunks of 256 elems (2 x 128-elem prefix segments per chunk).
// 4-deep rotating chunk prefetch => 8 LDG.128 (512B) in flight per lane.
// Circular shfl (lane+1 mod 32) provides halos AND lane31's deferred
// boundary data; packed dual-segment __reduce_add_sync per chunk.
// Windows: zc([128a,128b)) = S[b] - S[a] - bcorr[b].

#define T_LEN 4096
#define N_WIN 57
#define WARPS 8
#define PF    4
#define FULL  0xffffffffu

__global__ __launch_bounds__(256)
void petrosian_kernel(const float* __restrict__ x, float* __restrict__ out, int n_rows) {
    const int lane = threadIdx.x & 31;
    const int wid  = threadIdx.x >> 5;
    const int row  = blockIdx.x * WARPS + wid;
    if (row >= n_rows) return;

    const float4* p4 = (const float4*)(x + (size_t)row * T_LEN);

    // 4-chunk prefetch pipeline (8 LDG.128 in flight)
    float4 b0[PF], b1[PF];
    #pragma unroll
    for (int i = 0; i < PF; i++) {
        b0[i] = p4[64 * i + lane];
        b1[i] = p4[64 * i + 32 + lane];
    }

    int   segreg = 0, bcreg = 0;   // lane m: segment-m sum / bcorr[m+1]
    int   prevHigh = 0;
    float cx = 0.0f, cd = 0.0f;    // lane 31 carries: x[255], d[254] of prev chunk
    const int nl = (lane + 1) & 31;

    #pragma unroll
    for (int c = 0; c < 16; c++) {
        float4 v0 = b0[c & (PF - 1)], v1 = b1[c & (PF - 1)];
        if (c < 16 - PF) {
            b0[c & (PF - 1)] = p4[64 * (c + PF) + lane];
            b1[c & (PF - 1)] = p4[64 * (c + PF) + 32 + lane];
        }

        float h0x = __shfl_sync(FULL, v0.x, nl);
        float h0y = __shfl_sync(FULL, v0.y, nl);
        float h1x = __shfl_sync(FULL, v1.x, nl);
        float h1y = __shfl_sync(FULL, v1.y, nl);

        // deferred end-boundary of previous chunk: s[256c-2], s[256c-1]
        if (c > 0) {
            float dA = h0x - cx;        // d[256c-1]
            float dB = h0y - h0x;       // d[256c]
            int te = ((cd * dA < 0.0f) ? 1 : 0) + ((dA * dB < 0.0f) ? 1 : 0);
            te = __shfl_sync(FULL, te, 31);
            if (lane == 2 * c - 1) { segreg = prevHigh + te; bcreg = te; }
        }

        // low half: j = 256c + 4l + {0..3}; lane31 halo = lane0's v1
        float fhx = (lane < 31) ? h0x : h1x;
        float fhy = (lane < 31) ? h0y : h1y;
        float d0 = v0.y - v0.x, d1 = v0.z - v0.y, d2 = v0.w - v0.z;
        float d3 = fhx - v0.w,  d4 = fhy - fhx;
        int sl2 = (d2 * d3 < 0.0f) ? 1 : 0;
        int sl3 = (d3 * d4 < 0.0f) ? 1 : 0;
        int cntLow = ((d0 * d1 < 0.0f) ? 1 : 0) + ((d1 * d2 < 0.0f) ? 1 : 0) + sl2 + sl3;
        int tm = __shfl_sync(FULL, sl2 + sl3, 31);   // bcorr[2c+1] = s126+s127

        // high half: j = 256c + 128 + 4l + {0..3}; lane31: last 2 deferred
        float e0 = v1.y - v1.x, e1 = v1.z - v1.y, e2 = v1.w - v1.z;
        float e3 = h1x - v1.w,  e4 = h1y - h1x;
        int cntHigh = ((e0 * e1 < 0.0f) ? 1 : 0) + ((e1 * e2 < 0.0f) ? 1 : 0);
        if (lane < 31)
            cntHigh += ((e2 * e3 < 0.0f) ? 1 : 0) + ((e3 * e4 < 0.0f) ? 1 : 0);

        int total = __reduce_add_sync(FULL, cntLow | (cntHigh << 16));
        if (lane == 2 * c) { segreg = total & 0xFFFF; bcreg = tm; }
        prevHigh = total >> 16;

        // lane 31 carries for next chunk's deferred boundary
        cx = v1.w;   // x[256c+255]
        cd = e2;     // d[256c+254]
    }
    // final high segment (m=31): s[4094], s[4095] invalid -> te = 0
    if (lane == 31) { segreg = prevHigh; bcreg = 0; }

    // inclusive scan: sc at lane l = S[l+1]
    int sc = segreg;
    #pragma unroll
    for (int off = 1; off < 32; off <<= 1) {
        int n = __shfl_up_sync(FULL, sc, off);
        if (lane >= off) sc += n;
    }

    // 57 outputs, 2 per lane
    const size_t obase = (size_t)row * N_WIN;
    #pragma unroll
    for (int half = 0; half < 2; half++) {
        int k  = lane + half * 32;
        int kk = (k < N_WIN) ? k : 0;
        int w, a; float L;
        if      (kk < 1)  { w = 4096; a = 0;             L = 3.612359948f; }
        else if (kk < 4)  { w = 2048; a = (kk - 1) * 8;  L = 3.311329954f; }
        else if (kk < 11) { w = 1024; a = (kk - 4) * 4;  L = 3.010299957f; }
        else if (kk < 26) { w = 512;  a = (kk - 11) * 2; L = 2.709269961f; }
        else              { w = 256;  a = kk - 26;       L = 2.408239965f; }
        int b = a + (w >> 7);

        int Sb = __shfl_sync(FULL, sc, b - 1);
        int Sa = __shfl_sync(FULL, sc, (a > 0) ? (a - 1) : 0);
        if (a == 0) Sa = 0;
        int bc = __shfl_sync(FULL, bcreg, b - 1);

        if (k < N_WIN) {
            float zc = (float)(Sb - Sa - bc);
            float wf = (float)w;
            float denom = L + log10f(wf / (wf + 0.4f * zc));
            out[obase + k] = L / denom;
        }
    }
}

extern "C" void kernel_launch(void* const* d_in, const int* in_sizes, int n_in,
                              void* d_out, int out_size) {
    const float* x = (const float*)d_in[0];
    float* out = (float*)d_out;
    int n_rows = in_sizes[0] / T_LEN;               // B*C = 4096
    int n_blocks = (n_rows + WARPS - 1) / WARPS;    // 512
    petrosian_kernel<<<n_blocks, 256>>>(x, out, n_rows);
}